// round 2
// baseline (speedup 1.0000x reference)
#include <cuda_runtime.h>
#include <cuda_bf16.h>

// Problem constants (fixed by reference)
#define VOCAB      32000
#define EMBED_DIM  128
#define BATCH      32
#define MAX_TREES  512
#define NSEG       (BATCH * MAX_TREES)   // 16384

// Scratch: segment boundaries (device global — allocation-free)
__device__ int g_seg_start[NSEG + 1];

// ---------------------------------------------------------------------------
// Kernel 1: binary-search segment boundaries in the sorted tree_ids array.
// ---------------------------------------------------------------------------
__global__ void seg_bounds_kernel(const int* __restrict__ tree_ids, int n) {
    int s = blockIdx.x * blockDim.x + threadIdx.x;
    if (s > NSEG) return;
    int lo = 0, hi = n;
    while (lo < hi) {
        int mid = (lo + hi) >> 1;
        if (__ldg(&tree_ids[mid]) < s) lo = mid + 1;
        else hi = mid;
    }
    g_seg_start[s] = lo;
}

// ---------------------------------------------------------------------------
// Kernel 2: one warp per (segment, table). 32 lanes x float4 = full 128-float
// row. Token ids are fetched 32-at-a-time with one coalesced lane-parallel
// load and distributed via shuffle (kills per-token uniform-load wavefronts).
// Inner loop unrolled x8 for memory-level parallelism.
// ---------------------------------------------------------------------------
__global__ void __launch_bounds__(256)
seg_sum_kernel(const int*    __restrict__ token_ids,
               const float4* __restrict__ C_hop,    // [VOCAB][32] float4
               const float4* __restrict__ C_hop1,
               float4*       __restrict__ out)      // [2][NSEG][32] float4
{
    const int gw   = (blockIdx.x * blockDim.x + threadIdx.x) >> 5;
    const int lane = threadIdx.x & 31;
    if (gw >= 2 * NSEG) return;

    const int seg = gw >> 1;
    const int tbl = gw & 1;
    const float4* __restrict__ C = tbl ? C_hop1 : C_hop;

    const int beg = g_seg_start[seg];
    const int end = g_seg_start[seg + 1];

    float4 a = make_float4(0.f, 0.f, 0.f, 0.f);

    int base = beg;
    // Full 32-token chunks: one coalesced id load per chunk, shfl-distribute.
    for (; base + 32 <= end; base += 32) {
        const int myid = __ldg(&token_ids[base + lane]);
        #pragma unroll 8
        for (int u = 0; u < 32; u++) {
            int t = __shfl_sync(0xffffffffu, myid, u);
            float4 r = __ldg(&C[t * 32 + lane]);
            a.x += r.x; a.y += r.y; a.z += r.z; a.w += r.w;
        }
    }
    // Remainder chunk (< 32 tokens)
    if (base < end) {
        const int rem  = end - base;
        const int myid = (lane < rem) ? __ldg(&token_ids[base + lane]) : 0;
        for (int u = 0; u < rem; u++) {
            int t = __shfl_sync(0xffffffffu, myid, u);
            float4 r = __ldg(&C[t * 32 + lane]);
            a.x += r.x; a.y += r.y; a.z += r.z; a.w += r.w;
        }
    }

    // out layout: [2, NSEG, 32 float4]; key plane (tbl=0) first, then value.
    out[((size_t)tbl * NSEG + (size_t)seg) * 32 + lane] = a;
}

// ---------------------------------------------------------------------------
// Launch
// ---------------------------------------------------------------------------
extern "C" void kernel_launch(void* const* d_in, const int* in_sizes, int n_in,
                              void* d_out, int out_size) {
    const int*    token_ids = (const int*)   d_in[0];
    const int*    tree_ids  = (const int*)   d_in[1];
    const float4* C_hop     = (const float4*)d_in[2];
    const float4* C_hop1    = (const float4*)d_in[3];
    float4*       out       = (float4*)      d_out;

    const int n = in_sizes[0];  // TOTAL_TOKENS

    // Kernel 1: segment boundaries (16385 binary searches)
    {
        int threads = 256;
        int blocks  = (NSEG + 1 + threads - 1) / threads;
        seg_bounds_kernel<<<blocks, threads>>>(tree_ids, n);
    }

    // Kernel 2: one warp per (segment, table) -> 32768 warps = 4096 blocks
    {
        int threads = 256;
        int blocks  = (2 * NSEG * 32 + threads - 1) / threads;  // 4096
        seg_sum_kernel<<<blocks, threads>>>(token_ids, C_hop, C_hop1, out);
    }
}

// round 3
// speedup vs baseline: 1.0031x; 1.0031x over previous
#include <cuda_runtime.h>
#include <cuda_bf16.h>

// Problem constants (fixed by reference)
#define VOCAB      32000
#define EMBED_DIM  128
#define BATCH      32
#define MAX_TREES  512
#define NSEG       (BATCH * MAX_TREES)   // 16384

// Scratch: segment boundaries (device global — allocation-free)
__device__ int g_seg_start[NSEG + 1];

// ---------------------------------------------------------------------------
// Kernel 1: binary-search segment boundaries in the sorted tree_ids array.
// ---------------------------------------------------------------------------
__global__ void seg_bounds_kernel(const int* __restrict__ tree_ids, int n) {
    int s = blockIdx.x * blockDim.x + threadIdx.x;
    if (s > NSEG) return;
    int lo = 0, hi = n;
    while (lo < hi) {
        int mid = (lo + hi) >> 1;
        if (__ldg(&tree_ids[mid]) < s) lo = mid + 1;
        else hi = mid;
    }
    g_seg_start[s] = lo;
}

// ---------------------------------------------------------------------------
// Kernel 2: one warp per (segment, table). 32 lanes x float4 = full 128-float
// row per load. Row gathers use __ldcg (L2-only, bypass L1): the tables are a
// 32MB random working set, so L1 hit rate ~0 and L1 fills are pure overhead.
// Token ids are fetched 32-at-a-time coalesced and distributed via shuffle.
// Two accumulators halve the FADD dependency chain.
// ---------------------------------------------------------------------------
__global__ void __launch_bounds__(256)
seg_sum_kernel(const int*    __restrict__ token_ids,
               const float4* __restrict__ C_hop,    // [VOCAB][32] float4
               const float4* __restrict__ C_hop1,
               float4*       __restrict__ out)      // [2][NSEG][32] float4
{
    const int gw   = (blockIdx.x * blockDim.x + threadIdx.x) >> 5;
    const int lane = threadIdx.x & 31;
    if (gw >= 2 * NSEG) return;

    const int seg = gw >> 1;
    const int tbl = gw & 1;
    const float4* __restrict__ C = tbl ? C_hop1 : C_hop;

    const int beg = g_seg_start[seg];
    const int end = g_seg_start[seg + 1];

    float4 a0 = make_float4(0.f, 0.f, 0.f, 0.f);
    float4 a1 = make_float4(0.f, 0.f, 0.f, 0.f);

    int base = beg;
    // Full 32-token chunks: one coalesced id load per chunk, shfl-distribute.
    for (; base + 32 <= end; base += 32) {
        const int myid = __ldg(&token_ids[base + lane]);
        #pragma unroll
        for (int u = 0; u < 32; u += 2) {
            int t0 = __shfl_sync(0xffffffffu, myid, u);
            int t1 = __shfl_sync(0xffffffffu, myid, u + 1);
            float4 r0 = __ldcg(&C[t0 * 32 + lane]);
            float4 r1 = __ldcg(&C[t1 * 32 + lane]);
            a0.x += r0.x; a0.y += r0.y; a0.z += r0.z; a0.w += r0.w;
            a1.x += r1.x; a1.y += r1.y; a1.z += r1.z; a1.w += r1.w;
        }
    }
    // Remainder chunk (< 32 tokens)
    if (base < end) {
        const int rem  = end - base;
        const int myid = (lane < rem) ? __ldg(&token_ids[base + lane]) : 0;
        for (int u = 0; u < rem; u++) {
            int t = __shfl_sync(0xffffffffu, myid, u);
            float4 r = __ldcg(&C[t * 32 + lane]);
            a0.x += r.x; a0.y += r.y; a0.z += r.z; a0.w += r.w;
        }
    }

    a0.x += a1.x; a0.y += a1.y; a0.z += a1.z; a0.w += a1.w;

    // out layout: [2, NSEG, 32 float4]; key plane (tbl=0) first, then value.
    out[((size_t)tbl * NSEG + (size_t)seg) * 32 + lane] = a0;
}

// ---------------------------------------------------------------------------
// Launch
// ---------------------------------------------------------------------------
extern "C" void kernel_launch(void* const* d_in, const int* in_sizes, int n_in,
                              void* d_out, int out_size) {
    const int*    token_ids = (const int*)   d_in[0];
    const int*    tree_ids  = (const int*)   d_in[1];
    const float4* C_hop     = (const float4*)d_in[2];
    const float4* C_hop1    = (const float4*)d_in[3];
    float4*       out       = (float4*)      d_out;

    const int n = in_sizes[0];  // TOTAL_TOKENS

    // Kernel 1: segment boundaries (16385 binary searches)
    {
        int threads = 256;
        int blocks  = (NSEG + 1 + threads - 1) / threads;
        seg_bounds_kernel<<<blocks, threads>>>(tree_ids, n);
    }

    // Kernel 2: one warp per (segment, table) -> 32768 warps = 4096 blocks
    {
        int threads = 256;
        int blocks  = (2 * NSEG * 32 + threads - 1) / threads;  // 4096
        seg_sum_kernel<<<blocks, threads>>>(token_ids, C_hop, C_hop1, out);
    }
}